// round 8
// baseline (speedup 1.0000x reference)
#include <cuda_runtime.h>
#include <cuda_fp16.h>
#include <math.h>
#include <stdint.h>

#define Bb 128
#define Tt 576
#define Dd 1024
#define Hh 1024
#define Uu 512
#define Mm (Bb*Tt)   // 73728

// ---------------- scratch (device globals; no allocs allowed) ----------------
__device__ float  g_projh[Bb*Uu];       // hidden@W2 + W2_b + W1_b
__device__ float  g_score[Mm];
__device__ float  g_weights[Mm];
__device__ __half g_W1H[Dd*Uu];         // fp16 copy of W1 [D][U]  (1 MB)

// ---------------- helpers ----------------
__device__ __forceinline__ uint32_t smem_u32(const void* p){
    uint32_t a;
    asm("{ .reg .u64 t; cvta.to.shared.u64 t, %1; cvt.u32.u64 %0, t; }" : "=r"(a) : "l"(p));
    return a;
}
__device__ __forceinline__ uint32_t pack_h2(float x, float y){   // x -> low half
    uint32_t u;
    asm("cvt.rn.f16x2.f32 %0, %1, %2;" : "=r"(u) : "f"(y), "f"(x));
    return u;
}
__device__ __forceinline__ float tanh_fast(float x){
    float y;
    asm("tanh.approx.f32 %0, %1;" : "=f"(y) : "f"(x));
    return y;
}
__device__ __forceinline__ void ldsm_x4(uint32_t* r, uint32_t addr){
    asm volatile("ldmatrix.sync.aligned.m8n8.x4.shared.b16 {%0,%1,%2,%3}, [%4];"
        : "=r"(r[0]), "=r"(r[1]), "=r"(r[2]), "=r"(r[3]) : "r"(addr));
}
__device__ __forceinline__ void ldsm_x4_t(uint32_t* r, uint32_t addr){
    asm volatile("ldmatrix.sync.aligned.m8n8.x4.trans.shared.b16 {%0,%1,%2,%3}, [%4];"
        : "=r"(r[0]), "=r"(r[1]), "=r"(r[2]), "=r"(r[3]) : "r"(addr));
}
__device__ __forceinline__ void mma_f16(float* c, const uint32_t* a, const uint32_t* b){
    asm volatile(
        "mma.sync.aligned.m16n8k16.row.col.f32.f16.f16.f32 "
        "{%0,%1,%2,%3}, {%4,%5,%6,%7}, {%8,%9}, {%0,%1,%2,%3};"
        : "+f"(c[0]), "+f"(c[1]), "+f"(c[2]), "+f"(c[3])
        : "r"(a[0]), "r"(a[1]), "r"(a[2]), "r"(a[3]), "r"(b[0]), "r"(b[1]));
}
__device__ __forceinline__ void cp16(uint32_t dst, const void* src){
    asm volatile("cp.async.cg.shared.global [%0], [%1], 16;" :: "r"(dst), "l"(src));
}
__device__ __forceinline__ void cp_commit(){ asm volatile("cp.async.commit_group;" ::: "memory"); }

// ---------------- conversion kernel (W1 only; small) ----------------
__global__ void conv_w1_kernel(const float* __restrict__ W1){
    const size_t i = (size_t)blockIdx.x * blockDim.x + threadIdx.x;
    const float4 v = reinterpret_cast<const float4*>(W1)[i];
    uint2 u; u.x = pack_h2(v.x, v.y); u.y = pack_h2(v.z, v.w);
    reinterpret_cast<uint2*>(g_W1H)[i] = u;
}

// ---------------- zero score ----------------
__global__ void zero_score_kernel(){
    int i = blockIdx.x * blockDim.x + threadIdx.x;
    if (i < Mm) g_score[i] = 0.0f;
}

// ---------------- proj_h = hidden @ W2 + W2_b + W1_b (8 batches / block) ----------------
__global__ void projh_kernel(const float* __restrict__ hidden,
                             const float* __restrict__ W2,
                             const float* __restrict__ W2b,
                             const float* __restrict__ W1b){
    __shared__ float sh[8*Hh];
    const int b0 = blockIdx.x * 8;       // grid = 16
    const int u  = threadIdx.x;          // 512 threads
    for (int i = threadIdx.x; i < 8*Hh; i += blockDim.x)
        sh[i] = hidden[(size_t)b0*Hh + i];
    __syncthreads();
    float a[8] = {0,0,0,0,0,0,0,0};
    #pragma unroll 4
    for (int h = 0; h < Hh; ++h){
        const float w = W2[(size_t)h*Uu + u];
        #pragma unroll
        for (int j = 0; j < 8; ++j) a[j] += sh[j*Hh + h] * w;
    }
    const float bias = W1b[u] + W2b[u];
    #pragma unroll
    for (int j = 0; j < 8; ++j)
        g_projh[(size_t)(b0+j)*Uu + u] = a[j] + bias;
}

// ---------------- fp16 mma.sync GEMM + fused tanh·V epilogue ----------------
// CTA: BM=128 x BN=128, BK=32. 8 warps of 32x64. A: 2-buf LDG+cvt+STS (prefetch
// distance 2). B: 3-stage cp.async from fp16 W1. 2 CTAs/SM.
#define BM 128
#define BN 128
#define BK 32
#define SA_STR 40              // halves per A row (32 + 8 pad)
#define SB_STR 136             // halves per B row (128 + 8 pad)
#define SA_BYTES (BM*SA_STR*2) // 10240
#define SB_BYTES (BK*SB_STR*2) // 8704
#define NBSTG 3
#define GEMM_SMEM (2*SA_BYTES + NBSTG*SB_BYTES)   // 46592
#define NKT (Dd/BK)            // 32

extern __shared__ char smem_raw[];

__global__ void __launch_bounds__(256, 2)
gemm_score_kernel(const float* __restrict__ A,   // features fp32 [Mm, Dd]
                  const float* __restrict__ Vw)
{
    const uint32_t sbase = smem_u32(smem_raw);
    const uint32_t sB0   = sbase + 2*SA_BYTES;
    const int tid    = threadIdx.x;
    const int lane   = tid & 31;
    const int w      = tid >> 5;        // 8 warps
    const int warp_m = w >> 1;          // 0..3 : 32 rows
    const int warp_n = w & 1;           // 0..1 : 64 cols
    const int gid    = lane >> 2;
    const int tg     = lane & 3;
    const int m0     = blockIdx.y * BM; // gridDim.y = 576
    const int n0     = blockIdx.x * BN; // gridDim.x = 4 (adjacent bids share A in L2)

    // A staging: thread handles row = tid>>1, 16 k-values at kseg = (tid&1)*16
    const int arow  = tid >> 1;
    const int kseg  = (tid & 1) * 16;
    const float* aptr = A + (size_t)(m0 + arow)*Dd + kseg;

    float4 pf[4];                        // prefetched fp32 A
    auto ldA = [&](int kt){
        #pragma unroll
        for (int i = 0; i < 4; i++)
            pf[i] = *reinterpret_cast<const float4*>(aptr + kt*BK + i*4);
    };
    auto stA = [&](int buf){
        uint32_t u[8];
        #pragma unroll
        for (int i = 0; i < 4; i++){
            u[2*i]   = pack_h2(pf[i].x, pf[i].y);
            u[2*i+1] = pack_h2(pf[i].z, pf[i].w);
        }
        char* d = smem_raw + buf*SA_BYTES + (arow*SA_STR + kseg)*2;
        *reinterpret_cast<uint4*>(d)      = *reinterpret_cast<uint4*>(u);
        *reinterpret_cast<uint4*>(d + 16) = *reinterpret_cast<uint4*>(u + 4);
    };
    auto cpB = [&](int kt){             // one stage of B, one commit group
        const uint32_t bB = sB0 + (uint32_t)(kt % NBSTG)*SB_BYTES;
        #pragma unroll
        for (int i = 0; i < 2; i++){
            const int s = tid + i*256;
            const int krow = s >> 4, ch = s & 15;
            cp16(bB + (uint32_t)(krow*(SB_STR*2) + ch*16),
                 g_W1H + (size_t)(kt*BK + krow)*Uu + n0 + ch*8);
        }
        cp_commit();
    };

    float acc[2][8][4];
    #pragma unroll
    for (int i=0;i<2;i++)
        #pragma unroll
        for (int j=0;j<8;j++)
            #pragma unroll
            for (int k=0;k<4;k++) acc[i][j][k] = 0.0f;

    // prologue
    cpB(0); cpB(1); cpB(2);
    ldA(0); stA(0);
    ldA(1);
    __syncthreads();     // A buf0 visible

    for (int kt = 0; kt < NKT; ++kt){
        const int abuf = kt & 1;
        asm volatile("cp.async.wait_group %0;" :: "n"(NBSTG-1) : "memory");
        __syncthreads();                 // B[kt] visible; prev compute done

        // stage A(kt+1) into abuf^1 (safe: compute(kt-1) on abuf^1 finished)
        if (kt + 1 < NKT) stA(abuf ^ 1);
        if (kt + 2 < NKT) ldA(kt + 2);

        const uint32_t sA = sbase + (uint32_t)abuf*SA_BYTES;
        const uint32_t sB = sB0 + (uint32_t)(kt % NBSTG)*SB_BYTES;
        #pragma unroll
        for (int ks=0; ks<2; ks++){      // two k16 halves of BK=32
            uint32_t af[2][4], bf[8][2];
            #pragma unroll
            for (int mi=0;mi<2;mi++){
                uint32_t addr = sA + 2u*((warp_m*32 + mi*16 + (lane & 15))*SA_STR
                                          + ks*16 + (lane >> 4)*8);
                ldsm_x4(af[mi], addr);
            }
            #pragma unroll
            for (int np=0;np<4;np++){
                uint32_t r[4];
                uint32_t addr = sB + 2u*((ks*16 + (lane & 15))*SB_STR
                                          + warp_n*64 + np*16 + (lane >> 4)*8);
                ldsm_x4_t(r, addr);
                bf[2*np][0]   = r[0]; bf[2*np][1]   = r[1];
                bf[2*np+1][0] = r[2]; bf[2*np+1][1] = r[3];
            }
            #pragma unroll
            for (int mi=0;mi<2;mi++)
                #pragma unroll
                for (int ni=0;ni<8;ni++)
                    mma_f16(acc[mi][ni], af[mi], bf[ni]);
        }

        __syncthreads();                 // all warps done reading B[kt] buffer
        if (kt + NBSTG < NKT) cpB(kt + NBSTG);
        else                  cp_commit();   // keep group accounting uniform
    }

    // ----- epilogue: tanh + V contraction, quad-reduce, atomic accumulate -----
    const int nb = n0 + warp_n*64;
    #pragma unroll
    for (int mi=0; mi<2; mi++){
        #pragma unroll
        for (int h=0; h<2; h++){
            const int row = m0 + warp_m*32 + mi*16 + 8*h + gid;
            const int b   = row / Tt;
            const float* __restrict__ ph = g_projh + (size_t)b*Uu;   // has both biases
            float rsum = 0.0f;
            #pragma unroll
            for (int ni=0; ni<8; ni++){
                const int c0 = nb + ni*8 + tg*2;
                const float v0 = acc[mi][ni][2*h + 0] + ph[c0];
                const float v1 = acc[mi][ni][2*h + 1] + ph[c0 + 1];
                rsum += tanh_fast(v0) * Vw[c0] + tanh_fast(v1) * Vw[c0 + 1];
            }
            rsum += __shfl_xor_sync(0xffffffffu, rsum, 1);
            rsum += __shfl_xor_sync(0xffffffffu, rsum, 2);
            if (tg == 0) atomicAdd(&g_score[row], rsum);
        }
    }
}

// ---------------- softmax over T per batch ----------------
__global__ void softmax_kernel(float* __restrict__ w_out){
    const int b    = blockIdx.x;
    const int tid  = threadIdx.x;       // 576 threads
    const int lane = tid & 31;
    const int wid  = tid >> 5;
    __shared__ float sred[32];

    const float s = g_score[b*Tt + tid];

    float v = s;
    #pragma unroll
    for (int o=16;o>0;o>>=1) v = fmaxf(v, __shfl_xor_sync(0xffffffffu, v, o));
    if (lane == 0) sred[wid] = v;
    __syncthreads();
    if (tid < 32){
        float m = (tid < 18) ? sred[tid] : -3.4e38f;
        #pragma unroll
        for (int o=16;o>0;o>>=1) m = fmaxf(m, __shfl_xor_sync(0xffffffffu, m, o));
        sred[tid] = m;
    }
    __syncthreads();
    const float mx = sred[0];
    const float e  = expf(s - mx);
    __syncthreads();

    float t = e;
    #pragma unroll
    for (int o=16;o>0;o>>=1) t += __shfl_xor_sync(0xffffffffu, t, o);
    if (lane == 0) sred[wid] = t;
    __syncthreads();
    if (tid < 32){
        float su = (tid < 18) ? sred[tid] : 0.0f;
        #pragma unroll
        for (int o=16;o>0;o>>=1) su += __shfl_xor_sync(0xffffffffu, su, o);
        sred[tid] = su;
    }
    __syncthreads();
    const float total = sred[0];

    const float wgt = e / total;
    g_weights[b*Tt + tid] = wgt;
    if (w_out) w_out[b*Tt + tid] = wgt;
}

// ---------------- context = sum_t w[b,t] * features[b,t,:] ----------------
__global__ void context_kernel(const float* __restrict__ feat,
                               float* __restrict__ ctx){
    const int b = blockIdx.y;
    const int d = blockIdx.x * blockDim.x + threadIdx.x;
    __shared__ float sw[Tt];
    for (int t = threadIdx.x; t < Tt; t += blockDim.x) sw[t] = g_weights[b*Tt + t];
    __syncthreads();
    const float* fb = feat + (size_t)b*Tt*Dd + d;
    float acc = 0.0f;
    #pragma unroll 4
    for (int t = 0; t < Tt; ++t) acc += sw[t] * fb[(size_t)t*Dd];
    ctx[b*Dd + d] = acc;
}

// ---------------- launch ----------------
extern "C" void kernel_launch(void* const* d_in, const int* in_sizes, int n_in,
                              void* d_out, int out_size){
    const float* features = (const float*)d_in[0];
    const float* hidden   = (const float*)d_in[1];
    const float* W1w      = (const float*)d_in[2];
    const float* W1b      = (const float*)d_in[3];
    const float* W2w      = (const float*)d_in[4];
    const float* W2b      = (const float*)d_in[5];
    const float* Vw       = (const float*)d_in[6];
    // d_in[7] = V_b: softmax is shift-invariant -> cannot affect outputs.

    float* out = (float*)d_out;
    float* ctx_out = nullptr;
    float* w_out   = nullptr;
    if (out_size >= Bb*Dd + Mm)      { ctx_out = out; w_out = out + Bb*Dd; }
    else if (out_size == Bb*Dd)      { ctx_out = out; }
    else if (out_size == Mm)         { w_out = out; }
    else                             { ctx_out = out; }

    cudaFuncSetAttribute(gemm_score_kernel,
                         cudaFuncAttributeMaxDynamicSharedMemorySize, GEMM_SMEM);

    conv_w1_kernel<<<(Dd*Uu/4)/256, 256>>>(W1w);
    zero_score_kernel<<<Mm/256, 256>>>();
    projh_kernel<<<Bb/8, Uu>>>(hidden, W2w, W2b, W1b);

    dim3 gg(Uu/BN, Mm/BM);   // (4, 576)
    gemm_score_kernel<<<gg, 256, GEMM_SMEM>>>(features, Vw);

    softmax_kernel<<<Bb, Tt>>>(w_out);

    if (ctx_out){
        dim3 gc(Dd/256, Bb); // (4, 128)
        context_kernel<<<gc, 256>>>(features, ctx_out);
    }
}

// round 11
// speedup vs baseline: 1.6399x; 1.6399x over previous
#include <cuda_runtime.h>
#include <cuda_fp16.h>
#include <math.h>
#include <stdint.h>

#define Bb 128
#define Tt 576
#define Dd 1024
#define Hh 1024
#define Uu 512
#define Mm (Bb*Tt)   // 73728

// ---------------- scratch (device globals; no allocs allowed) ----------------
__device__ float  g_projh[Bb*Uu];       // hidden@W2 + W2_b + W1_b
__device__ float  g_score[Mm];
__device__ float  g_weights[Mm];
__device__ __half g_W1H[Dd*Uu];         // fp16 copy of W1 [D][U]  (1 MB)

// ---------------- helpers ----------------
__device__ __forceinline__ uint32_t smem_u32(const void* p){
    uint32_t a;
    asm("{ .reg .u64 t; cvta.to.shared.u64 t, %1; cvt.u32.u64 %0, t; }" : "=r"(a) : "l"(p));
    return a;
}
__device__ __forceinline__ uint32_t pack_h2(float x, float y){   // x -> low half
    uint32_t u;
    asm("cvt.rn.f16x2.f32 %0, %1, %2;" : "=r"(u) : "f"(y), "f"(x));
    return u;
}
__device__ __forceinline__ float tanh_fast(float x){
    float y;
    asm("tanh.approx.f32 %0, %1;" : "=f"(y) : "f"(x));
    return y;
}
__device__ __forceinline__ void ldsm_x4(uint32_t* r, uint32_t addr){
    asm volatile("ldmatrix.sync.aligned.m8n8.x4.shared.b16 {%0,%1,%2,%3}, [%4];"
        : "=r"(r[0]), "=r"(r[1]), "=r"(r[2]), "=r"(r[3]) : "r"(addr));
}
__device__ __forceinline__ void ldsm_x4_t(uint32_t* r, uint32_t addr){
    asm volatile("ldmatrix.sync.aligned.m8n8.x4.trans.shared.b16 {%0,%1,%2,%3}, [%4];"
        : "=r"(r[0]), "=r"(r[1]), "=r"(r[2]), "=r"(r[3]) : "r"(addr));
}
__device__ __forceinline__ void mma_f16(float* c, const uint32_t* a, const uint32_t* b){
    asm volatile(
        "mma.sync.aligned.m16n8k16.row.col.f32.f16.f16.f32 "
        "{%0,%1,%2,%3}, {%4,%5,%6,%7}, {%8,%9}, {%0,%1,%2,%3};"
        : "+f"(c[0]), "+f"(c[1]), "+f"(c[2]), "+f"(c[3])
        : "r"(a[0]), "r"(a[1]), "r"(a[2]), "r"(a[3]), "r"(b[0]), "r"(b[1]));
}
__device__ __forceinline__ void cp16(uint32_t dst, const void* src){
    asm volatile("cp.async.cg.shared.global [%0], [%1], 16;" :: "r"(dst), "l"(src));
}
__device__ __forceinline__ void cp_commit(){ asm volatile("cp.async.commit_group;" ::: "memory"); }

// ---------------- conversion kernel (W1 only; small) ----------------
__global__ void conv_w1_kernel(const float* __restrict__ W1){
    const size_t i = (size_t)blockIdx.x * blockDim.x + threadIdx.x;
    const float4 v = reinterpret_cast<const float4*>(W1)[i];
    uint2 u; u.x = pack_h2(v.x, v.y); u.y = pack_h2(v.z, v.w);
    reinterpret_cast<uint2*>(g_W1H)[i] = u;
}

// ---------------- zero score ----------------
__global__ void zero_score_kernel(){
    int i = blockIdx.x * blockDim.x + threadIdx.x;
    if (i < Mm) g_score[i] = 0.0f;
}

// ---------------- proj_h = hidden @ W2 + W2_b + W1_b ----------------
// grid (128 b, 4 u-chunks), 128 threads: 512 blocks -> full SM coverage.
__global__ void projh_kernel(const float* __restrict__ hidden,
                             const float* __restrict__ W2,
                             const float* __restrict__ W2b,
                             const float* __restrict__ W1b){
    __shared__ float sh[Hh];
    const int b = blockIdx.x;
    const int u = blockIdx.y * 128 + threadIdx.x;
    #pragma unroll
    for (int i = 0; i < 8; i++)
        sh[threadIdx.x + i*128] = hidden[(size_t)b*Hh + threadIdx.x + i*128];
    __syncthreads();
    float acc = 0.0f;
    #pragma unroll 8
    for (int h = 0; h < Hh; ++h)
        acc += sh[h] * W2[(size_t)h*Uu + u];
    g_projh[(size_t)b*Uu + u] = acc + W1b[u] + W2b[u];
}

// ---------------- fp16 mma.sync GEMM + fused tanh·V epilogue ----------------
// CTA: BM=256 x BN=128, BK=32. 8 warps of 64x64 (128B LDS per MMA).
// A: fp32 LDG -> cvt -> STS, 2-buffer, prefetch distance 2.
// B: 4-stage cp.async ring from fp16 W1.  ONE __syncthreads per kt.
#define BM 256
#define BN 128
#define BK 32
#define SA_STR 40              // halves per A row (32 + 8 pad)
#define SB_STR 136             // halves per B row (128 + 8 pad)
#define SA_BYTES (BM*SA_STR*2) // 20480
#define SB_BYTES (BK*SB_STR*2) // 8704
#define NBSTG 4
#define GEMM_SMEM (2*SA_BYTES + NBSTG*SB_BYTES)   // 75776
#define NKT (Dd/BK)            // 32

extern __shared__ char smem_raw[];

__global__ void __launch_bounds__(256, 1)
gemm_score_kernel(const float* __restrict__ A,   // features fp32 [Mm, Dd]
                  const float* __restrict__ Vw)
{
    const uint32_t sbase = smem_u32(smem_raw);
    const uint32_t sB0   = sbase + 2*SA_BYTES;
    const int tid    = threadIdx.x;
    const int lane   = tid & 31;
    const int w      = tid >> 5;        // 8 warps
    const int warp_m = w >> 1;          // 0..3 : 64 rows
    const int warp_n = w & 1;           // 0..1 : 64 cols
    const int gid    = lane >> 2;
    const int tg     = lane & 3;
    const int m0     = blockIdx.y * BM; // gridDim.y = 288
    const int n0     = blockIdx.x * BN; // gridDim.x = 4 (adjacent bids share A in L2)

    // A staging: thread owns chunk ch = tid&7 (4 floats of k), rows (tid>>3) + 32*i
    const int ach = tid & 7;
    const int ar0 = tid >> 3;
    const float* aptr = A + (size_t)(m0 + ar0)*Dd + ach*4;

    float4 pf[8];                        // prefetched fp32 A (rows ar0 + 32i)
    auto ldA = [&](int kt){
        #pragma unroll
        for (int i = 0; i < 8; i++)
            pf[i] = *reinterpret_cast<const float4*>(aptr + (size_t)(32*i)*Dd + kt*BK);
    };
    auto stA = [&](int buf){
        char* base = smem_raw + buf*SA_BYTES;
        #pragma unroll
        for (int i = 0; i < 8; i++){
            uint2 u; u.x = pack_h2(pf[i].x, pf[i].y); u.y = pack_h2(pf[i].z, pf[i].w);
            *reinterpret_cast<uint2*>(base + ((ar0 + 32*i)*SA_STR + ach*4)*2) = u;
        }
    };
    auto cpB = [&](int kt){             // one stage of B, one commit group
        const uint32_t bB = sB0 + (uint32_t)(kt % NBSTG)*SB_BYTES;
        #pragma unroll
        for (int i = 0; i < 2; i++){
            const int s = tid + i*256;
            const int krow = s >> 4, ch = s & 15;
            cp16(bB + (uint32_t)(krow*(SB_STR*2) + ch*16),
                 g_W1H + (size_t)(kt*BK + krow)*Uu + n0 + ch*8);
        }
        cp_commit();
    };

    float acc[4][8][4];
    #pragma unroll
    for (int i=0;i<4;i++)
        #pragma unroll
        for (int j=0;j<8;j++)
            #pragma unroll
            for (int k=0;k<4;k++) acc[i][j][k] = 0.0f;

    // prologue: 3 B groups in flight; A buf0 staged; A(1) in registers
    cpB(0); cpB(1); cpB(2);
    ldA(0); stA(0);
    ldA(1);

    for (int kt = 0; kt < NKT; ++kt){
        asm volatile("cp.async.wait_group %0;" :: "n"(2) : "memory");  // B[kt] ready
        __syncthreads();   // compute(kt-1) done everywhere; stA(kt) visible

        if (kt + 1 < NKT) stA((kt + 1) & 1);    // buf (kt-1)&1: free after barrier
        if (kt + 2 < NKT) ldA(kt + 2);
        if (kt + 3 < NKT) cpB(kt + 3);          // B buf (kt-1)%4: free after barrier
        else              cp_commit();          // keep group accounting uniform

        const uint32_t sA = sbase + (uint32_t)(kt & 1)*SA_BYTES;
        const uint32_t sB = sB0 + (uint32_t)(kt % NBSTG)*SB_BYTES;
        #pragma unroll
        for (int ks=0; ks<2; ks++){      // two k16 halves of BK=32
            uint32_t af[4][4], bf[8][2];
            #pragma unroll
            for (int mi=0;mi<4;mi++){
                uint32_t addr = sA + 2u*((warp_m*64 + mi*16 + (lane & 15))*SA_STR
                                          + ks*16 + (lane >> 4)*8);
                ldsm_x4(af[mi], addr);
            }
            #pragma unroll
            for (int np=0;np<4;np++){
                uint32_t r[4];
                uint32_t addr = sB + 2u*((ks*16 + (lane & 15))*SB_STR
                                          + warp_n*64 + np*16 + (lane >> 4)*8);
                ldsm_x4_t(r, addr);
                bf[2*np][0]   = r[0]; bf[2*np][1]   = r[1];
                bf[2*np+1][0] = r[2]; bf[2*np+1][1] = r[3];
            }
            #pragma unroll
            for (int mi=0;mi<4;mi++)
                #pragma unroll
                for (int ni=0;ni<8;ni++)
                    mma_f16(acc[mi][ni], af[mi], bf[ni]);
        }
    }

    // ----- epilogue: tanh + V contraction, quad-reduce, atomic accumulate -----
    const int nb = n0 + warp_n*64;
    #pragma unroll
    for (int mi=0; mi<4; mi++){
        #pragma unroll
        for (int h=0; h<2; h++){
            const int row = m0 + warp_m*64 + mi*16 + 8*h + gid;
            const int b   = row / Tt;
            const float* __restrict__ ph = g_projh + (size_t)b*Uu;   // has both biases
            float rsum = 0.0f;
            #pragma unroll
            for (int ni=0; ni<8; ni++){
                const int c0 = nb + ni*8 + tg*2;
                const float v0 = acc[mi][ni][2*h + 0] + ph[c0];
                const float v1 = acc[mi][ni][2*h + 1] + ph[c0 + 1];
                rsum += tanh_fast(v0) * Vw[c0] + tanh_fast(v1) * Vw[c0 + 1];
            }
            rsum += __shfl_xor_sync(0xffffffffu, rsum, 1);
            rsum += __shfl_xor_sync(0xffffffffu, rsum, 2);
            if (tg == 0) atomicAdd(&g_score[row], rsum);
        }
    }
}

// ---------------- softmax over T per batch ----------------
__global__ void softmax_kernel(float* __restrict__ w_out){
    const int b    = blockIdx.x;
    const int tid  = threadIdx.x;       // 576 threads
    const int lane = tid & 31;
    const int wid  = tid >> 5;
    __shared__ float sred[32];

    const float s = g_score[b*Tt + tid];

    float v = s;
    #pragma unroll
    for (int o=16;o>0;o>>=1) v = fmaxf(v, __shfl_xor_sync(0xffffffffu, v, o));
    if (lane == 0) sred[wid] = v;
    __syncthreads();
    if (tid < 32){
        float m = (tid < 18) ? sred[tid] : -3.4e38f;
        #pragma unroll
        for (int o=16;o>0;o>>=1) m = fmaxf(m, __shfl_xor_sync(0xffffffffu, m, o));
        sred[tid] = m;
    }
    __syncthreads();
    const float mx = sred[0];
    const float e  = expf(s - mx);
    __syncthreads();

    float t = e;
    #pragma unroll
    for (int o=16;o>0;o>>=1) t += __shfl_xor_sync(0xffffffffu, t, o);
    if (lane == 0) sred[wid] = t;
    __syncthreads();
    if (tid < 32){
        float su = (tid < 18) ? sred[tid] : 0.0f;
        #pragma unroll
        for (int o=16;o>0;o>>=1) su += __shfl_xor_sync(0xffffffffu, su, o);
        sred[tid] = su;
    }
    __syncthreads();
    const float total = sred[0];

    const float wgt = e / total;
    g_weights[b*Tt + tid] = wgt;
    if (w_out) w_out[b*Tt + tid] = wgt;
}

// ---------------- context = sum_t w[b,t] * features[b,t,:] ----------------
__global__ void context_kernel(const float* __restrict__ feat,
                               float* __restrict__ ctx){
    const int b = blockIdx.y;
    const int d = blockIdx.x * blockDim.x + threadIdx.x;
    __shared__ float sw[Tt];
    for (int t = threadIdx.x; t < Tt; t += blockDim.x) sw[t] = g_weights[b*Tt + t];
    __syncthreads();
    const float* fb = feat + (size_t)b*Tt*Dd + d;
    float acc = 0.0f;
    #pragma unroll 4
    for (int t = 0; t < Tt; ++t) acc += sw[t] * fb[(size_t)t*Dd];
    ctx[b*Dd + d] = acc;
}

// ---------------- launch ----------------
extern "C" void kernel_launch(void* const* d_in, const int* in_sizes, int n_in,
                              void* d_out, int out_size){
    const float* features = (const float*)d_in[0];
    const float* hidden   = (const float*)d_in[1];
    const float* W1w      = (const float*)d_in[2];
    const float* W1b      = (const float*)d_in[3];
    const float* W2w      = (const float*)d_in[4];
    const float* W2b      = (const float*)d_in[5];
    const float* Vw       = (const float*)d_in[6];
    // d_in[7] = V_b: softmax is shift-invariant -> cannot affect outputs.

    float* out = (float*)d_out;
    float* ctx_out = nullptr;
    float* w_out   = nullptr;
    if (out_size >= Bb*Dd + Mm)      { ctx_out = out; w_out = out + Bb*Dd; }
    else if (out_size == Bb*Dd)      { ctx_out = out; }
    else if (out_size == Mm)         { w_out = out; }
    else                             { ctx_out = out; }

    cudaFuncSetAttribute(gemm_score_kernel,
                         cudaFuncAttributeMaxDynamicSharedMemorySize, GEMM_SMEM);

    conv_w1_kernel<<<(Dd*Uu/4)/256, 256>>>(W1w);
    zero_score_kernel<<<Mm/256, 256>>>();
    projh_kernel<<<dim3(Bb, 4), 128>>>(hidden, W2w, W2b, W1b);

    dim3 gg(Uu/BN, Mm/BM);   // (4, 288)
    gemm_score_kernel<<<gg, 256, GEMM_SMEM>>>(features, Vw);

    softmax_kernel<<<Bb, Tt>>>(w_out);

    if (ctx_out){
        dim3 gc(Dd/256, Bb); // (4, 128)
        context_kernel<<<gc, 256>>>(features, ctx_out);
    }
}

// round 12
// speedup vs baseline: 2.1985x; 1.3406x over previous
#include <cuda_runtime.h>
#include <cuda_fp16.h>
#include <math.h>
#include <stdint.h>

#define Bb 128
#define Tt 576
#define Dd 1024
#define Hh 1024
#define Uu 512
#define Mm (Bb*Tt)   // 73728

// ---------------- scratch (device globals; no allocs allowed) ----------------
__device__ float  g_projh[Bb*Uu];        // hidden@W2 + W2_b + W1_b
__device__ float  g_score8[8*Mm];        // 8 partial score slices (no atomics)
__device__ float  g_weights[Mm];
__device__ __half g_W1H[Dd*Uu];          // fp16 copy of W1 [D][U]  (1 MB)

// ---------------- helpers ----------------
__device__ __forceinline__ uint32_t smem_u32(const void* p){
    uint32_t a;
    asm("{ .reg .u64 t; cvta.to.shared.u64 t, %1; cvt.u32.u64 %0, t; }" : "=r"(a) : "l"(p));
    return a;
}
__device__ __forceinline__ uint32_t pack_h2(float x, float y){   // x -> low half
    uint32_t u;
    asm("cvt.rn.f16x2.f32 %0, %1, %2;" : "=r"(u) : "f"(y), "f"(x));
    return u;
}
__device__ __forceinline__ float tanh_fast(float x){
    float y;
    asm("tanh.approx.f32 %0, %1;" : "=f"(y) : "f"(x));
    return y;
}
__device__ __forceinline__ void ldsm_x4(uint32_t* r, uint32_t addr){
    asm volatile("ldmatrix.sync.aligned.m8n8.x4.shared.b16 {%0,%1,%2,%3}, [%4];"
        : "=r"(r[0]), "=r"(r[1]), "=r"(r[2]), "=r"(r[3]) : "r"(addr));
}
__device__ __forceinline__ void ldsm_x4_t(uint32_t* r, uint32_t addr){
    asm volatile("ldmatrix.sync.aligned.m8n8.x4.trans.shared.b16 {%0,%1,%2,%3}, [%4];"
        : "=r"(r[0]), "=r"(r[1]), "=r"(r[2]), "=r"(r[3]) : "r"(addr));
}
__device__ __forceinline__ void mma_f16(float* c, const uint32_t* a, const uint32_t* b){
    asm volatile(
        "mma.sync.aligned.m16n8k16.row.col.f32.f16.f16.f32 "
        "{%0,%1,%2,%3}, {%4,%5,%6,%7}, {%8,%9}, {%0,%1,%2,%3};"
        : "+f"(c[0]), "+f"(c[1]), "+f"(c[2]), "+f"(c[3])
        : "r"(a[0]), "r"(a[1]), "r"(a[2]), "r"(a[3]), "r"(b[0]), "r"(b[1]));
}
__device__ __forceinline__ void cp16(uint32_t dst, const void* src){
    asm volatile("cp.async.cg.shared.global [%0], [%1], 16;" :: "r"(dst), "l"(src));
}
__device__ __forceinline__ void cp_commit(){ asm volatile("cp.async.commit_group;" ::: "memory"); }

// ---------------- conversion kernel (W1 only; small) ----------------
__global__ void conv_w1_kernel(const float* __restrict__ W1){
    const size_t i = (size_t)blockIdx.x * blockDim.x + threadIdx.x;
    const float4 v = reinterpret_cast<const float4*>(W1)[i];
    uint2 u; u.x = pack_h2(v.x, v.y); u.y = pack_h2(v.z, v.w);
    reinterpret_cast<uint2*>(g_W1H)[i] = u;
}

// ---------------- proj_h = hidden @ W2 + W2_b + W1_b ----------------
// grid (128 b, 8 u-blocks of 64), 256 threads = (64 u, 4-way k-split).
__global__ void __launch_bounds__(256)
projh_kernel(const float* __restrict__ hidden,
             const float* __restrict__ W2,
             const float* __restrict__ W2b,
             const float* __restrict__ W1b){
    __shared__ float sh[Hh];
    __shared__ float red[256];
    const int b  = blockIdx.x;
    const int ul = threadIdx.x & 63;
    const int kq = threadIdx.x >> 6;          // 0..3
    const int u  = blockIdx.y * 64 + ul;
    #pragma unroll
    for (int i = 0; i < 4; i++)
        sh[threadIdx.x + i*256] = hidden[(size_t)b*Hh + threadIdx.x + i*256];
    __syncthreads();
    float acc = 0.0f;
    const int h0 = kq * 256;
    #pragma unroll 8
    for (int h = 0; h < 256; ++h)
        acc += sh[h0 + h] * W2[(size_t)(h0 + h)*Uu + u];
    red[threadIdx.x] = acc;
    __syncthreads();
    if (kq == 0){
        const float tot = red[ul] + red[64 + ul] + red[128 + ul] + red[192 + ul];
        g_projh[(size_t)b*Uu + u] = tot + W1b[u] + W2b[u];
    }
}

// ---------------- fp16 mma.sync GEMM + fused tanh·V epilogue ----------------
// CTA: BM=256 x BN=128, BK=32. 8 warps of 64x64 (128B LDS per MMA).
// A: fp32 LDG -> cvt -> STS, 2-buffer, prefetch distance 2.
// B: 4-stage cp.async ring from fp16 W1.  ONE __syncthreads per kt.
// Fragment-level pipelining: both ks B-fragment sets prefetched up front.
#define BM 256
#define BN 128
#define BK 32
#define SA_STR 40              // halves per A row (32 + 8 pad)
#define SB_STR 136             // halves per B row (128 + 8 pad)
#define SA_BYTES (BM*SA_STR*2) // 20480
#define SB_BYTES (BK*SB_STR*2) // 8704
#define NBSTG 4
#define GEMM_SMEM (2*SA_BYTES + NBSTG*SB_BYTES)   // 75776
#define NKT (Dd/BK)            // 32

extern __shared__ char smem_raw[];

__global__ void __launch_bounds__(256, 1)
gemm_score_kernel(const float* __restrict__ A,   // features fp32 [Mm, Dd]
                  const float* __restrict__ Vw)
{
    const uint32_t sbase = smem_u32(smem_raw);
    const uint32_t sB0   = sbase + 2*SA_BYTES;
    const int tid    = threadIdx.x;
    const int lane   = tid & 31;
    const int w      = tid >> 5;        // 8 warps
    const int warp_m = w >> 1;          // 0..3 : 64 rows
    const int warp_n = w & 1;           // 0..1 : 64 cols
    const int gid    = lane >> 2;
    const int tg     = lane & 3;
    const int m0     = blockIdx.y * BM; // gridDim.y = 288
    const int n0     = blockIdx.x * BN; // gridDim.x = 4 (adjacent bids share A in L2)

    // A staging: thread owns chunk ch = tid&7 (4 floats of k), rows (tid>>3) + 32*i
    const int ach = tid & 7;
    const int ar0 = tid >> 3;
    const float* aptr = A + (size_t)(m0 + ar0)*Dd + ach*4;

    float4 pf[8];                        // prefetched fp32 A (rows ar0 + 32i)
    auto ldA = [&](int kt){
        #pragma unroll
        for (int i = 0; i < 8; i++)
            pf[i] = *reinterpret_cast<const float4*>(aptr + (size_t)(32*i)*Dd + kt*BK);
    };
    auto stA = [&](int buf){
        char* base = smem_raw + buf*SA_BYTES;
        #pragma unroll
        for (int i = 0; i < 8; i++){
            uint2 u; u.x = pack_h2(pf[i].x, pf[i].y); u.y = pack_h2(pf[i].z, pf[i].w);
            *reinterpret_cast<uint2*>(base + ((ar0 + 32*i)*SA_STR + ach*4)*2) = u;
        }
    };
    auto cpB = [&](int kt){             // one stage of B, one commit group
        const uint32_t bB = sB0 + (uint32_t)(kt % NBSTG)*SB_BYTES;
        #pragma unroll
        for (int i = 0; i < 2; i++){
            const int s = tid + i*256;
            const int krow = s >> 4, ch = s & 15;
            cp16(bB + (uint32_t)(krow*(SB_STR*2) + ch*16),
                 g_W1H + (size_t)(kt*BK + krow)*Uu + n0 + ch*8);
        }
        cp_commit();
    };

    float acc[4][8][4];
    #pragma unroll
    for (int i=0;i<4;i++)
        #pragma unroll
        for (int j=0;j<8;j++)
            #pragma unroll
            for (int k=0;k<4;k++) acc[i][j][k] = 0.0f;

    // fragment loaders
    const uint32_t a_lane_off = 2u*((warp_m*64 + (lane & 15))*SA_STR + (lane >> 4)*8);
    const uint32_t b_lane_off = 2u*((lane & 15)*SB_STR + warp_n*64 + (lane >> 4)*8);

    auto ldAf = [&](uint32_t af[4][4], uint32_t sA, int ks){
        #pragma unroll
        for (int mi=0;mi<4;mi++)
            ldsm_x4(af[mi], sA + a_lane_off + 2u*(mi*16*SA_STR + ks*16));
    };
    auto ldBf = [&](uint32_t bf[8][2], uint32_t sB, int ks){
        #pragma unroll
        for (int np=0;np<4;np++){
            uint32_t r[4];
            ldsm_x4_t(r, sB + b_lane_off + 2u*(ks*16*SB_STR + np*16));
            bf[2*np][0]   = r[0]; bf[2*np][1]   = r[1];
            bf[2*np+1][0] = r[2]; bf[2*np+1][1] = r[3];
        }
    };

    // prologue: 3 B groups in flight; A buf0 staged; A(1) in registers
    cpB(0); cpB(1); cpB(2);
    ldA(0); stA(0);
    ldA(1);

    for (int kt = 0; kt < NKT; ++kt){
        asm volatile("cp.async.wait_group %0;" :: "n"(2) : "memory");  // B[kt] ready
        __syncthreads();   // compute(kt-1) done everywhere; stA(kt) visible

        if (kt + 1 < NKT) stA((kt + 1) & 1);    // buf (kt-1)&1: free after barrier
        if (kt + 2 < NKT) ldA(kt + 2);
        if (kt + 3 < NKT) cpB(kt + 3);          // B buf (kt-1)%4: free after barrier
        else              cp_commit();          // keep group accounting uniform

        const uint32_t sA = sbase + (uint32_t)(kt & 1)*SA_BYTES;
        const uint32_t sB = sB0 + (uint32_t)(kt % NBSTG)*SB_BYTES;

        uint32_t af[4][4], bf0[8][2], bf1[8][2];
        ldBf(bf0, sB, 0);            // 12 LDSM issued back-to-back: latencies overlap
        ldAf(af,  sA, 0);
        ldBf(bf1, sB, 1);
        #pragma unroll
        for (int mi=0;mi<4;mi++)
            #pragma unroll
            for (int ni=0;ni<8;ni++)
                mma_f16(acc[mi][ni], af[mi], bf0[ni]);
        ldAf(af, sA, 1);             // overlaps tail of ks0 MMA stream
        #pragma unroll
        for (int mi=0;mi<4;mi++)
            #pragma unroll
            for (int ni=0;ni<8;ni++)
                mma_f16(acc[mi][ni], af[mi], bf1[ni]);
    }

    // ----- epilogue: tanh + V contraction, quad-reduce, direct partial store -----
    const int nb   = n0 + warp_n*64;
    const int part = blockIdx.x*2 + warp_n;          // 0..7
    #pragma unroll
    for (int mi=0; mi<4; mi++){
        #pragma unroll
        for (int h=0; h<2; h++){
            const int row = m0 + warp_m*64 + mi*16 + 8*h + gid;
            const int b   = row / Tt;
            const float* __restrict__ ph = g_projh + (size_t)b*Uu;   // has both biases
            float rsum = 0.0f;
            #pragma unroll
            for (int ni=0; ni<8; ni++){
                const int c0 = nb + ni*8 + tg*2;
                const float v0 = acc[mi][ni][2*h + 0] + ph[c0];
                const float v1 = acc[mi][ni][2*h + 1] + ph[c0 + 1];
                rsum += tanh_fast(v0) * Vw[c0] + tanh_fast(v1) * Vw[c0 + 1];
            }
            rsum += __shfl_xor_sync(0xffffffffu, rsum, 1);
            rsum += __shfl_xor_sync(0xffffffffu, rsum, 2);
            if (tg == 0) g_score8[(size_t)part*Mm + row] = rsum;
        }
    }
}

// ---------------- softmax over T per batch (sums 8 partial slices) ----------------
__global__ void softmax_kernel(float* __restrict__ w_out){
    const int b    = blockIdx.x;
    const int tid  = threadIdx.x;       // 576 threads
    const int lane = tid & 31;
    const int wid  = tid >> 5;
    __shared__ float sred[32];

    float s = 0.0f;
    #pragma unroll
    for (int i = 0; i < 8; i++)
        s += g_score8[(size_t)i*Mm + b*Tt + tid];

    float v = s;
    #pragma unroll
    for (int o=16;o>0;o>>=1) v = fmaxf(v, __shfl_xor_sync(0xffffffffu, v, o));
    if (lane == 0) sred[wid] = v;
    __syncthreads();
    if (tid < 32){
        float m = (tid < 18) ? sred[tid] : -3.4e38f;
        #pragma unroll
        for (int o=16;o>0;o>>=1) m = fmaxf(m, __shfl_xor_sync(0xffffffffu, m, o));
        sred[tid] = m;
    }
    __syncthreads();
    const float mx = sred[0];
    const float e  = expf(s - mx);
    __syncthreads();

    float t = e;
    #pragma unroll
    for (int o=16;o>0;o>>=1) t += __shfl_xor_sync(0xffffffffu, t, o);
    if (lane == 0) sred[wid] = t;
    __syncthreads();
    if (tid < 32){
        float su = (tid < 18) ? sred[tid] : 0.0f;
        #pragma unroll
        for (int o=16;o>0;o>>=1) su += __shfl_xor_sync(0xffffffffu, su, o);
        sred[tid] = su;
    }
    __syncthreads();
    const float total = sred[0];

    const float wgt = e / total;
    g_weights[b*Tt + tid] = wgt;
    if (w_out) w_out[b*Tt + tid] = wgt;
}

// ---------------- context = sum_t w[b,t] * features[b,t,:] ----------------
// grid (8, 128), 128 threads: 1024 blocks, unroll 8, 4 accumulators.
__global__ void __launch_bounds__(128)
context_kernel(const float* __restrict__ feat,
               float* __restrict__ ctx){
    const int b = blockIdx.y;
    const int d = blockIdx.x * 128 + threadIdx.x;
    __shared__ float sw[Tt];
    #pragma unroll
    for (int i = 0; i < 5; i++){
        const int t = threadIdx.x + i*128;
        if (t < Tt) sw[t] = g_weights[b*Tt + t];
    }
    __syncthreads();
    const float* fb = feat + (size_t)b*Tt*Dd + d;
    float a0 = 0.f, a1 = 0.f, a2 = 0.f, a3 = 0.f;
    #pragma unroll 2
    for (int t = 0; t < Tt; t += 8){
        a0 += sw[t+0] * fb[(size_t)(t+0)*Dd];
        a1 += sw[t+1] * fb[(size_t)(t+1)*Dd];
        a2 += sw[t+2] * fb[(size_t)(t+2)*Dd];
        a3 += sw[t+3] * fb[(size_t)(t+3)*Dd];
        a0 += sw[t+4] * fb[(size_t)(t+4)*Dd];
        a1 += sw[t+5] * fb[(size_t)(t+5)*Dd];
        a2 += sw[t+6] * fb[(size_t)(t+6)*Dd];
        a3 += sw[t+7] * fb[(size_t)(t+7)*Dd];
    }
    ctx[b*Dd + d] = (a0 + a1) + (a2 + a3);
}

// ---------------- launch ----------------
extern "C" void kernel_launch(void* const* d_in, const int* in_sizes, int n_in,
                              void* d_out, int out_size){
    const float* features = (const float*)d_in[0];
    const float* hidden   = (const float*)d_in[1];
    const float* W1w      = (const float*)d_in[2];
    const float* W1b      = (const float*)d_in[3];
    const float* W2w      = (const float*)d_in[4];
    const float* W2b      = (const float*)d_in[5];
    const float* Vw       = (const float*)d_in[6];
    // d_in[7] = V_b: softmax is shift-invariant -> cannot affect outputs.

    float* out = (float*)d_out;
    float* ctx_out = nullptr;
    float* w_out   = nullptr;
    if (out_size >= Bb*Dd + Mm)      { ctx_out = out; w_out = out + Bb*Dd; }
    else if (out_size == Bb*Dd)      { ctx_out = out; }
    else if (out_size == Mm)         { w_out = out; }
    else                             { ctx_out = out; }

    cudaFuncSetAttribute(gemm_score_kernel,
                         cudaFuncAttributeMaxDynamicSharedMemorySize, GEMM_SMEM);

    conv_w1_kernel<<<(Dd*Uu/4)/256, 256>>>(W1w);
    projh_kernel<<<dim3(Bb, 8), 256>>>(hidden, W2w, W2b, W1b);

    dim3 gg(Uu/BN, Mm/BM);   // (4, 288)
    gemm_score_kernel<<<gg, 256, GEMM_SMEM>>>(features, Vw);

    softmax_kernel<<<Bb, Tt>>>(w_out);

    if (ctx_out){
        dim3 gc(Dd/128, Bb); // (8, 128)
        context_kernel<<<gc, 128>>>(features, ctx_out);
    }
}

// round 14
// speedup vs baseline: 2.2232x; 1.0112x over previous
#include <cuda_runtime.h>
#include <cuda_fp16.h>
#include <math.h>
#include <stdint.h>

#define Bb 128
#define Tt 576
#define Dd 1024
#define Hh 1024
#define Uu 512
#define Mm (Bb*Tt)   // 73728

// ---------------- scratch (device globals; no allocs allowed) ----------------
__device__ float  g_projh[Bb*Uu];        // hidden@W2 + W2_b + W1_b
__device__ float  g_score8[8*Mm];        // 8 partial score slices (no atomics)
__device__ float  g_weights[Mm];
__device__ __half g_W1H[Dd*Uu];          // fp16 copy of W1 [D][U]  (1 MB)

// ---------------- helpers ----------------
__device__ __forceinline__ uint32_t smem_u32(const void* p){
    uint32_t a;
    asm("{ .reg .u64 t; cvta.to.shared.u64 t, %1; cvt.u32.u64 %0, t; }" : "=r"(a) : "l"(p));
    return a;
}
__device__ __forceinline__ uint32_t pack_h2(float x, float y){   // x -> low half
    uint32_t u;
    asm("cvt.rn.f16x2.f32 %0, %1, %2;" : "=r"(u) : "f"(y), "f"(x));
    return u;
}
__device__ __forceinline__ float tanh_fast(float x){
    float y;
    asm("tanh.approx.f32 %0, %1;" : "=f"(y) : "f"(x));
    return y;
}
__device__ __forceinline__ void ldsm_x4(uint32_t* r, uint32_t addr){
    asm volatile("ldmatrix.sync.aligned.m8n8.x4.shared.b16 {%0,%1,%2,%3}, [%4];"
        : "=r"(r[0]), "=r"(r[1]), "=r"(r[2]), "=r"(r[3]) : "r"(addr));
}
__device__ __forceinline__ void ldsm_x4_t(uint32_t* r, uint32_t addr){
    asm volatile("ldmatrix.sync.aligned.m8n8.x4.trans.shared.b16 {%0,%1,%2,%3}, [%4];"
        : "=r"(r[0]), "=r"(r[1]), "=r"(r[2]), "=r"(r[3]) : "r"(addr));
}
__device__ __forceinline__ void mma_f16(float* c, const uint32_t* a, const uint32_t* b){
    asm volatile(
        "mma.sync.aligned.m16n8k16.row.col.f32.f16.f16.f32 "
        "{%0,%1,%2,%3}, {%4,%5,%6,%7}, {%8,%9}, {%0,%1,%2,%3};"
        : "+f"(c[0]), "+f"(c[1]), "+f"(c[2]), "+f"(c[3])
        : "r"(a[0]), "r"(a[1]), "r"(a[2]), "r"(a[3]), "r"(b[0]), "r"(b[1]));
}
__device__ __forceinline__ void cp16(uint32_t dst, const void* src){
    asm volatile("cp.async.cg.shared.global [%0], [%1], 16;" :: "r"(dst), "l"(src));
}
__device__ __forceinline__ void cp_commit(){ asm volatile("cp.async.commit_group;" ::: "memory"); }

// ---------------- conversion kernel (W1 only; small) ----------------
__global__ void conv_w1_kernel(const float* __restrict__ W1){
    const size_t i = (size_t)blockIdx.x * blockDim.x + threadIdx.x;
    const float4 v = reinterpret_cast<const float4*>(W1)[i];
    uint2 u; u.x = pack_h2(v.x, v.y); u.y = pack_h2(v.z, v.w);
    reinterpret_cast<uint2*>(g_W1H)[i] = u;
}

// ---------------- proj_h = hidden @ W2 + W2_b + W1_b ----------------
// grid (128 b, 8 u-blocks of 64), 256 threads = (64 u, 4-way k-split).
__global__ void __launch_bounds__(256)
projh_kernel(const float* __restrict__ hidden,
             const float* __restrict__ W2,
             const float* __restrict__ W2b,
             const float* __restrict__ W1b){
    __shared__ float sh[Hh];
    __shared__ float red[256];
    const int b  = blockIdx.x;
    const int ul = threadIdx.x & 63;
    const int kq = threadIdx.x >> 6;          // 0..3
    const int u  = blockIdx.y * 64 + ul;
    #pragma unroll
    for (int i = 0; i < 4; i++)
        sh[threadIdx.x + i*256] = hidden[(size_t)b*Hh + threadIdx.x + i*256];
    __syncthreads();
    float acc = 0.0f;
    const int h0 = kq * 256;
    #pragma unroll 8
    for (int h = 0; h < 256; ++h)
        acc += sh[h0 + h] * W2[(size_t)(h0 + h)*Uu + u];
    red[threadIdx.x] = acc;
    __syncthreads();
    if (kq == 0){
        const float tot = red[ul] + red[64 + ul] + red[128 + ul] + red[192 + ul];
        g_projh[(size_t)b*Uu + u] = tot + W1b[u] + W2b[u];
    }
}

// ---------------- fp16 mma.sync GEMM + fused tanh·V epilogue ----------------
// CTA: BM=256 x BN=128, BK=32. 8 warps of 64x64 (128B LDS per MMA).
// A: fp32 LDG -> cvt -> STS, 2-buffer, prefetch distance 2.
// B: 4-stage cp.async ring from fp16 W1.  ONE __syncthreads per kt.
// Mainloop = round-11 structure (238 regs, no spill). Epilogue: partial stores.
#define BM 256
#define BN 128
#define BK 32
#define SA_STR 40              // halves per A row (32 + 8 pad)
#define SB_STR 136             // halves per B row (128 + 8 pad)
#define SA_BYTES (BM*SA_STR*2) // 20480
#define SB_BYTES (BK*SB_STR*2) // 8704
#define NBSTG 4
#define GEMM_SMEM (2*SA_BYTES + NBSTG*SB_BYTES)   // 75776
#define NKT (Dd/BK)            // 32

extern __shared__ char smem_raw[];

__global__ void __launch_bounds__(256, 1)
gemm_score_kernel(const float* __restrict__ A,   // features fp32 [Mm, Dd]
                  const float* __restrict__ Vw)
{
    const uint32_t sbase = smem_u32(smem_raw);
    const uint32_t sB0   = sbase + 2*SA_BYTES;
    const int tid    = threadIdx.x;
    const int lane   = tid & 31;
    const int w      = tid >> 5;        // 8 warps
    const int warp_m = w >> 1;          // 0..3 : 64 rows
    const int warp_n = w & 1;           // 0..1 : 64 cols
    const int gid    = lane >> 2;
    const int tg     = lane & 3;
    const int m0     = blockIdx.y * BM; // gridDim.y = 288
    const int n0     = blockIdx.x * BN; // gridDim.x = 4 (adjacent bids share A in L2)

    // A staging: thread owns chunk ch = tid&7 (4 floats of k), rows (tid>>3) + 32*i
    const int ach = tid & 7;
    const int ar0 = tid >> 3;
    const float* aptr = A + (size_t)(m0 + ar0)*Dd + ach*4;

    float4 pf[8];                        // prefetched fp32 A (rows ar0 + 32i)
    auto ldA = [&](int kt){
        #pragma unroll
        for (int i = 0; i < 8; i++)
            pf[i] = *reinterpret_cast<const float4*>(aptr + (size_t)(32*i)*Dd + kt*BK);
    };
    auto stA = [&](int buf){
        char* base = smem_raw + buf*SA_BYTES;
        #pragma unroll
        for (int i = 0; i < 8; i++){
            uint2 u; u.x = pack_h2(pf[i].x, pf[i].y); u.y = pack_h2(pf[i].z, pf[i].w);
            *reinterpret_cast<uint2*>(base + ((ar0 + 32*i)*SA_STR + ach*4)*2) = u;
        }
    };
    auto cpB = [&](int kt){             // one stage of B, one commit group
        const uint32_t bB = sB0 + (uint32_t)(kt % NBSTG)*SB_BYTES;
        #pragma unroll
        for (int i = 0; i < 2; i++){
            const int s = tid + i*256;
            const int krow = s >> 4, ch = s & 15;
            cp16(bB + (uint32_t)(krow*(SB_STR*2) + ch*16),
                 g_W1H + (size_t)(kt*BK + krow)*Uu + n0 + ch*8);
        }
        cp_commit();
    };

    float acc[4][8][4];
    #pragma unroll
    for (int i=0;i<4;i++)
        #pragma unroll
        for (int j=0;j<8;j++)
            #pragma unroll
            for (int k=0;k<4;k++) acc[i][j][k] = 0.0f;

    // prologue: 3 B groups in flight; A buf0 staged; A(1) in registers
    cpB(0); cpB(1); cpB(2);
    ldA(0); stA(0);
    ldA(1);

    for (int kt = 0; kt < NKT; ++kt){
        asm volatile("cp.async.wait_group %0;" :: "n"(2) : "memory");  // B[kt] ready
        __syncthreads();   // compute(kt-1) done everywhere; stA(kt) visible

        if (kt + 1 < NKT) stA((kt + 1) & 1);    // buf (kt-1)&1: free after barrier
        if (kt + 2 < NKT) ldA(kt + 2);
        if (kt + 3 < NKT) cpB(kt + 3);          // B buf (kt-1)%4: free after barrier
        else              cp_commit();          // keep group accounting uniform

        const uint32_t sA = sbase + (uint32_t)(kt & 1)*SA_BYTES;
        const uint32_t sB = sB0 + (uint32_t)(kt % NBSTG)*SB_BYTES;
        #pragma unroll
        for (int ks=0; ks<2; ks++){      // two k16 halves of BK=32 (round-11 structure)
            uint32_t af[4][4], bf[8][2];
            #pragma unroll
            for (int mi=0;mi<4;mi++){
                uint32_t addr = sA + 2u*((warp_m*64 + mi*16 + (lane & 15))*SA_STR
                                          + ks*16 + (lane >> 4)*8);
                ldsm_x4(af[mi], addr);
            }
            #pragma unroll
            for (int np=0;np<4;np++){
                uint32_t r[4];
                uint32_t addr = sB + 2u*((ks*16 + (lane & 15))*SB_STR
                                          + warp_n*64 + np*16 + (lane >> 4)*8);
                ldsm_x4_t(r, addr);
                bf[2*np][0]   = r[0]; bf[2*np][1]   = r[1];
                bf[2*np+1][0] = r[2]; bf[2*np+1][1] = r[3];
            }
            #pragma unroll
            for (int mi=0;mi<4;mi++)
                #pragma unroll
                for (int ni=0;ni<8;ni++)
                    mma_f16(acc[mi][ni], af[mi], bf[ni]);
        }
    }

    // ----- epilogue: tanh + V contraction, quad-reduce, direct partial store -----
    const int nb   = n0 + warp_n*64;
    const int part = blockIdx.x*2 + warp_n;          // 0..7
    #pragma unroll
    for (int mi=0; mi<4; mi++){
        #pragma unroll
        for (int h=0; h<2; h++){
            const int row = m0 + warp_m*64 + mi*16 + 8*h + gid;
            const int b   = row / Tt;
            const float* __restrict__ ph = g_projh + (size_t)b*Uu;   // has both biases
            float rsum = 0.0f;
            #pragma unroll
            for (int ni=0; ni<8; ni++){
                const int c0 = nb + ni*8 + tg*2;
                const float v0 = acc[mi][ni][2*h + 0] + ph[c0];
                const float v1 = acc[mi][ni][2*h + 1] + ph[c0 + 1];
                rsum += tanh_fast(v0) * Vw[c0] + tanh_fast(v1) * Vw[c0 + 1];
            }
            rsum += __shfl_xor_sync(0xffffffffu, rsum, 1);
            rsum += __shfl_xor_sync(0xffffffffu, rsum, 2);
            if (tg == 0) g_score8[(size_t)part*Mm + row] = rsum;
        }
    }
}

// ---------------- softmax over T per batch (sums 8 partial slices) ----------------
__global__ void softmax_kernel(float* __restrict__ w_out){
    const int b    = blockIdx.x;
    const int tid  = threadIdx.x;       // 576 threads
    const int lane = tid & 31;
    const int wid  = tid >> 5;
    __shared__ float sred[32];

    float s = 0.0f;
    #pragma unroll
    for (int i = 0; i < 8; i++)
        s += g_score8[(size_t)i*Mm + b*Tt + tid];

    float v = s;
    #pragma unroll
    for (int o=16;o>0;o>>=1) v = fmaxf(v, __shfl_xor_sync(0xffffffffu, v, o));
    if (lane == 0) sred[wid] = v;
    __syncthreads();
    if (tid < 32){
        float m = (tid < 18) ? sred[tid] : -3.4e38f;
        #pragma unroll
        for (int o=16;o>0;o>>=1) m = fmaxf(m, __shfl_xor_sync(0xffffffffu, m, o));
        sred[tid] = m;
    }
    __syncthreads();
    const float mx = sred[0];
    const float e  = expf(s - mx);
    __syncthreads();

    float t = e;
    #pragma unroll
    for (int o=16;o>0;o>>=1) t += __shfl_xor_sync(0xffffffffu, t, o);
    if (lane == 0) sred[wid] = t;
    __syncthreads();
    if (tid < 32){
        float su = (tid < 18) ? sred[tid] : 0.0f;
        #pragma unroll
        for (int o=16;o>0;o>>=1) su += __shfl_xor_sync(0xffffffffu, su, o);
        sred[tid] = su;
    }
    __syncthreads();
    const float total = sred[0];

    const float wgt = e / total;
    g_weights[b*Tt + tid] = wgt;
    if (w_out) w_out[b*Tt + tid] = wgt;
}

// ---------------- context = sum_t w[b,t] * features[b,t,:] ----------------
// grid (8, 128), 128 threads: 1024 blocks, unroll 8, 4 accumulators.
__global__ void __launch_bounds__(128)
context_kernel(const float* __restrict__ feat,
               float* __restrict__ ctx){
    const int b = blockIdx.y;
    const int d = blockIdx.x * 128 + threadIdx.x;
    __shared__ float sw[Tt];
    #pragma unroll
    for (int i = 0; i < 5; i++){
        const int t = threadIdx.x + i*128;
        if (t < Tt) sw[t] = g_weights[b*Tt + t];
    }
    __syncthreads();
    const float* fb = feat + (size_t)b*Tt*Dd + d;
    float a0 = 0.f, a1 = 0.f, a2 = 0.f, a3 = 0.f;
    #pragma unroll 2
    for (int t = 0; t < Tt; t += 8){
        a0 += sw[t+0] * fb[(size_t)(t+0)*Dd];
        a1 += sw[t+1] * fb[(size_t)(t+1)*Dd];
        a2 += sw[t+2] * fb[(size_t)(t+2)*Dd];
        a3 += sw[t+3] * fb[(size_t)(t+3)*Dd];
        a0 += sw[t+4] * fb[(size_t)(t+4)*Dd];
        a1 += sw[t+5] * fb[(size_t)(t+5)*Dd];
        a2 += sw[t+6] * fb[(size_t)(t+6)*Dd];
        a3 += sw[t+7] * fb[(size_t)(t+7)*Dd];
    }
    ctx[b*Dd + d] = (a0 + a1) + (a2 + a3);
}

// ---------------- launch ----------------
extern "C" void kernel_launch(void* const* d_in, const int* in_sizes, int n_in,
                              void* d_out, int out_size){
    const float* features = (const float*)d_in[0];
    const float* hidden   = (const float*)d_in[1];
    const float* W1w      = (const float*)d_in[2];
    const float* W1b      = (const float*)d_in[3];
    const float* W2w      = (const float*)d_in[4];
    const float* W2b      = (const float*)d_in[5];
    const float* Vw       = (const float*)d_in[6];
    // d_in[7] = V_b: softmax is shift-invariant -> cannot affect outputs.

    float* out = (float*)d_out;
    float* ctx_out = nullptr;
    float* w_out   = nullptr;
    if (out_size >= Bb*Dd + Mm)      { ctx_out = out; w_out = out + Bb*Dd; }
    else if (out_size == Bb*Dd)      { ctx_out = out; }
    else if (out_size == Mm)         { w_out = out; }
    else                             { ctx_out = out; }

    cudaFuncSetAttribute(gemm_score_kernel,
                         cudaFuncAttributeMaxDynamicSharedMemorySize, GEMM_SMEM);

    conv_w1_kernel<<<(Dd*Uu/4)/256, 256>>>(W1w);
    projh_kernel<<<dim3(Bb, 8), 256>>>(hidden, W2w, W2b, W1b);

    dim3 gg(Uu/BN, Mm/BM);   // (4, 288)
    gemm_score_kernel<<<gg, 256, GEMM_SMEM>>>(features, Vw);

    softmax_kernel<<<Bb, Tt>>>(w_out);

    if (ctx_out){
        dim3 gc(Dd/128, Bb); // (8, 128)
        context_kernel<<<gc, 128>>>(features, ctx_out);
    }
}

// round 16
// speedup vs baseline: 2.3006x; 1.0348x over previous
#include <cuda_runtime.h>
#include <cuda_fp16.h>
#include <math.h>
#include <stdint.h>

#define Bb 128
#define Tt 576
#define Dd 1024
#define Hh 1024
#define Uu 512
#define Mm (Bb*Tt)   // 73728

// ---------------- scratch (device globals; no allocs allowed) ----------------
__device__ float  g_projh[Bb*Uu];        // hidden@W2 + W2_b + W1_b
__device__ float  g_score8[8*Mm];        // 8 partial score slices (no atomics)
__device__ float  g_weights[Mm];
__device__ __half g_W1H[Dd*Uu];          // fp16 copy of W1 [D][U]  (1 MB)

// ---------------- helpers ----------------
__device__ __forceinline__ uint32_t smem_u32(const void* p){
    uint32_t a;
    asm("{ .reg .u64 t; cvta.to.shared.u64 t, %1; cvt.u32.u64 %0, t; }" : "=r"(a) : "l"(p));
    return a;
}
__device__ __forceinline__ uint32_t pack_h2(float x, float y){   // x -> low half
    uint32_t u;
    asm("cvt.rn.f16x2.f32 %0, %1, %2;" : "=r"(u) : "f"(y), "f"(x));
    return u;
}
__device__ __forceinline__ float tanh_fast(float x){
    float y;
    asm("tanh.approx.f32 %0, %1;" : "=f"(y) : "f"(x));
    return y;
}
__device__ __forceinline__ void ldsm_x4(uint32_t* r, uint32_t addr){
    asm volatile("ldmatrix.sync.aligned.m8n8.x4.shared.b16 {%0,%1,%2,%3}, [%4];"
        : "=r"(r[0]), "=r"(r[1]), "=r"(r[2]), "=r"(r[3]) : "r"(addr));
}
__device__ __forceinline__ void ldsm_x4_t(uint32_t* r, uint32_t addr){
    asm volatile("ldmatrix.sync.aligned.m8n8.x4.trans.shared.b16 {%0,%1,%2,%3}, [%4];"
        : "=r"(r[0]), "=r"(r[1]), "=r"(r[2]), "=r"(r[3]) : "r"(addr));
}
__device__ __forceinline__ void mma_f16(float* c, const uint32_t* a, const uint32_t* b){
    asm volatile(
        "mma.sync.aligned.m16n8k16.row.col.f32.f16.f16.f32 "
        "{%0,%1,%2,%3}, {%4,%5,%6,%7}, {%8,%9}, {%0,%1,%2,%3};"
        : "+f"(c[0]), "+f"(c[1]), "+f"(c[2]), "+f"(c[3])
        : "r"(a[0]), "r"(a[1]), "r"(a[2]), "r"(a[3]), "r"(b[0]), "r"(b[1]));
}
__device__ __forceinline__ void cp16(uint32_t dst, const void* src){
    asm volatile("cp.async.cg.shared.global [%0], [%1], 16;" :: "r"(dst), "l"(src));
}
__device__ __forceinline__ void cp_commit(){ asm volatile("cp.async.commit_group;" ::: "memory"); }

// ---------------- conversion kernel (W1 only; small) ----------------
__global__ void conv_w1_kernel(const float* __restrict__ W1){
    const size_t i = (size_t)blockIdx.x * blockDim.x + threadIdx.x;
    const float4 v = reinterpret_cast<const float4*>(W1)[i];
    uint2 u; u.x = pack_h2(v.x, v.y); u.y = pack_h2(v.z, v.w);
    reinterpret_cast<uint2*>(g_W1H)[i] = u;
}

// ---------------- proj_h = hidden @ W2 + W2_b + W1_b ----------------
// grid (128 b, 8 u-blocks of 64), 256 threads = (64 u, 4-way k-split).
__global__ void __launch_bounds__(256)
projh_kernel(const float* __restrict__ hidden,
             const float* __restrict__ W2,
             const float* __restrict__ W2b,
             const float* __restrict__ W1b){
    __shared__ float sh[Hh];
    __shared__ float red[256];
    const int b  = blockIdx.x;
    const int ul = threadIdx.x & 63;
    const int kq = threadIdx.x >> 6;          // 0..3
    const int u  = blockIdx.y * 64 + ul;
    #pragma unroll
    for (int i = 0; i < 4; i++)
        sh[threadIdx.x + i*256] = hidden[(size_t)b*Hh + threadIdx.x + i*256];
    __syncthreads();
    float acc = 0.0f;
    const int h0 = kq * 256;
    #pragma unroll 8
    for (int h = 0; h < 256; ++h)
        acc += sh[h0 + h] * W2[(size_t)(h0 + h)*Uu + u];
    red[threadIdx.x] = acc;
    __syncthreads();
    if (kq == 0){
        const float tot = red[ul] + red[64 + ul] + red[128 + ul] + red[192 + ul];
        g_projh[(size_t)b*Uu + u] = tot + W1b[u] + W2b[u];
    }
}

// ---------------- fp16 mma.sync GEMM + fused tanh·V epilogue ----------------
// CTA: BM=256 x BN=128, BK=32. 8 warps of 64x64 (128B LDS per MMA).
// A: fp32 LDG -> cvt -> STS, 2-buffer, prefetch distance 2.
// B: 4-stage cp.async ring from fp16 W1.  ONE __syncthreads per kt.
// NEW: warp-parity ks stagger — even warps do k16-half 0 then 1, odd warps
// 1 then 0, so on each SMSP one warp's MMA burst overlaps the other's LDSM
// burst (tensor pipe stays fed through the fragment-load phases).
#define BM 256
#define BN 128
#define BK 32
#define SA_STR 40              // halves per A row (32 + 8 pad)
#define SB_STR 136             // halves per B row (128 + 8 pad)
#define SA_BYTES (BM*SA_STR*2) // 20480
#define SB_BYTES (BK*SB_STR*2) // 8704
#define NBSTG 4
#define GEMM_SMEM (2*SA_BYTES + NBSTG*SB_BYTES)   // 75776
#define NKT (Dd/BK)            // 32

extern __shared__ char smem_raw[];

__global__ void __launch_bounds__(256, 1)
gemm_score_kernel(const float* __restrict__ A,   // features fp32 [Mm, Dd]
                  const float* __restrict__ Vw)
{
    const uint32_t sbase = smem_u32(smem_raw);
    const uint32_t sB0   = sbase + 2*SA_BYTES;
    const int tid    = threadIdx.x;
    const int lane   = tid & 31;
    const int w      = tid >> 5;        // 8 warps
    const int warp_m = w >> 1;          // 0..3 : 64 rows
    const int warp_n = w & 1;           // 0..1 : 64 cols
    const int gid    = lane >> 2;
    const int tg     = lane & 3;
    const int m0     = blockIdx.y * BM; // gridDim.y = 288
    const int n0     = blockIdx.x * BN; // gridDim.x = 4 (adjacent bids share A in L2)
    const int kfirst = w & 1;           // SMSP phase stagger (w and w+4 share SMSP w%4;
                                        // co-resident warps w, w+4 have SAME parity only if...
                                        // wid%4 pairs are (w, w+4): parities differ when w<4 vs w+4 even/odd same.
                                        // (w & 1) differs between e.g. warps 1 and 4? pairs sharing SMSP are
                                        // {0,4},{1,5},{2,6},{3,7}: parity equal within pair -> use bit2 instead.
    const int krot   = (w >> 2) & 1;    // warps 0-3 vs 4-7: these differ within each SMSP pair

    // A staging: thread owns chunk ch = tid&7 (4 floats of k), rows (tid>>3) + 32*i
    const int ach = tid & 7;
    const int ar0 = tid >> 3;
    const float* aptr = A + (size_t)(m0 + ar0)*Dd + ach*4;

    float4 pf[8];                        // prefetched fp32 A (rows ar0 + 32i)
    auto ldA = [&](int kt){
        #pragma unroll
        for (int i = 0; i < 8; i++)
            pf[i] = *reinterpret_cast<const float4*>(aptr + (size_t)(32*i)*Dd + kt*BK);
    };
    auto stA = [&](int buf){
        char* base = smem_raw + buf*SA_BYTES;
        #pragma unroll
        for (int i = 0; i < 8; i++){
            uint2 u; u.x = pack_h2(pf[i].x, pf[i].y); u.y = pack_h2(pf[i].z, pf[i].w);
            *reinterpret_cast<uint2*>(base + ((ar0 + 32*i)*SA_STR + ach*4)*2) = u;
        }
    };
    auto cpB = [&](int kt){             // one stage of B, one commit group
        const uint32_t bB = sB0 + (uint32_t)(kt % NBSTG)*SB_BYTES;
        #pragma unroll
        for (int i = 0; i < 2; i++){
            const int s = tid + i*256;
            const int krow = s >> 4, ch = s & 15;
            cp16(bB + (uint32_t)(krow*(SB_STR*2) + ch*16),
                 g_W1H + (size_t)(kt*BK + krow)*Uu + n0 + ch*8);
        }
        cp_commit();
    };

    float acc[4][8][4];
    #pragma unroll
    for (int i=0;i<4;i++)
        #pragma unroll
        for (int j=0;j<8;j++)
            #pragma unroll
            for (int k=0;k<4;k++) acc[i][j][k] = 0.0f;

    // prologue: 3 B groups in flight; A buf0 staged; A(1) in registers
    cpB(0); cpB(1); cpB(2);
    ldA(0); stA(0);
    ldA(1);

    for (int kt = 0; kt < NKT; ++kt){
        asm volatile("cp.async.wait_group %0;" :: "n"(2) : "memory");  // B[kt] ready
        __syncthreads();   // compute(kt-1) done everywhere; stA(kt) visible

        if (kt + 1 < NKT) stA((kt + 1) & 1);    // buf (kt-1)&1: free after barrier
        if (kt + 2 < NKT) ldA(kt + 2);
        if (kt + 3 < NKT) cpB(kt + 3);          // B buf (kt-1)%4: free after barrier
        else              cp_commit();          // keep group accounting uniform

        const uint32_t sA = sbase + (uint32_t)(kt & 1)*SA_BYTES;
        const uint32_t sB = sB0 + (uint32_t)(kt % NBSTG)*SB_BYTES;
        #pragma unroll
        for (int kss=0; kss<2; kss++){   // staggered k16 halves of BK=32
            const int ks = kss ^ krot;   // SMSP co-residents take opposite order
            uint32_t af[4][4], bf[8][2];
            #pragma unroll
            for (int mi=0;mi<4;mi++){
                uint32_t addr = sA + 2u*((warp_m*64 + mi*16 + (lane & 15))*SA_STR
                                          + ks*16 + (lane >> 4)*8);
                ldsm_x4(af[mi], addr);
            }
            #pragma unroll
            for (int np=0;np<4;np++){
                uint32_t r[4];
                uint32_t addr = sB + 2u*((ks*16 + (lane & 15))*SB_STR
                                          + warp_n*64 + np*16 + (lane >> 4)*8);
                ldsm_x4_t(r, addr);
                bf[2*np][0]   = r[0]; bf[2*np][1]   = r[1];
                bf[2*np+1][0] = r[2]; bf[2*np+1][1] = r[3];
            }
            #pragma unroll
            for (int mi=0;mi<4;mi++)
                #pragma unroll
                for (int ni=0;ni<8;ni++)
                    mma_f16(acc[mi][ni], af[mi], bf[ni]);
        }
    }

    // ----- epilogue: tanh + V contraction, quad-reduce, direct partial store -----
    const int nb   = n0 + warp_n*64;
    const int part = blockIdx.x*2 + warp_n;          // 0..7
    #pragma unroll
    for (int mi=0; mi<4; mi++){
        #pragma unroll
        for (int h=0; h<2; h++){
            const int row = m0 + warp_m*64 + mi*16 + 8*h + gid;
            const int b   = row / Tt;
            const float* __restrict__ ph = g_projh + (size_t)b*Uu;   // has both biases
            float rsum = 0.0f;
            #pragma unroll
            for (int ni=0; ni<8; ni++){
                const int c0 = nb + ni*8 + tg*2;
                const float v0 = acc[mi][ni][2*h + 0] + ph[c0];
                const float v1 = acc[mi][ni][2*h + 1] + ph[c0 + 1];
                rsum += tanh_fast(v0) * Vw[c0] + tanh_fast(v1) * Vw[c0 + 1];
            }
            rsum += __shfl_xor_sync(0xffffffffu, rsum, 1);
            rsum += __shfl_xor_sync(0xffffffffu, rsum, 2);
            if (tg == 0) g_score8[(size_t)part*Mm + row] = rsum;
        }
    }
}

// ---------------- softmax over T per batch (sums 8 partial slices) ----------------
__global__ void softmax_kernel(float* __restrict__ w_out){
    const int b    = blockIdx.x;
    const int tid  = threadIdx.x;       // 576 threads
    const int lane = tid & 31;
    const int wid  = tid >> 5;
    __shared__ float sred[32];

    float s = 0.0f;
    #pragma unroll
    for (int i = 0; i < 8; i++)
        s += g_score8[(size_t)i*Mm + b*Tt + tid];

    float v = s;
    #pragma unroll
    for (int o=16;o>0;o>>=1) v = fmaxf(v, __shfl_xor_sync(0xffffffffu, v, o));
    if (lane == 0) sred[wid] = v;
    __syncthreads();
    if (tid < 32){
        float m = (tid < 18) ? sred[tid] : -3.4e38f;
        #pragma unroll
        for (int o=16;o>0;o>>=1) m = fmaxf(m, __shfl_xor_sync(0xffffffffu, m, o));
        sred[tid] = m;
    }
    __syncthreads();
    const float mx = sred[0];
    const float e  = expf(s - mx);
    __syncthreads();

    float t = e;
    #pragma unroll
    for (int o=16;o>0;o>>=1) t += __shfl_xor_sync(0xffffffffu, t, o);
    if (lane == 0) sred[wid] = t;
    __syncthreads();
    if (tid < 32){
        float su = (tid < 18) ? sred[tid] : 0.0f;
        #pragma unroll
        for (int o=16;o>0;o>>=1) su += __shfl_xor_sync(0xffffffffu, su, o);
        sred[tid] = su;
    }
    __syncthreads();
    const float total = sred[0];

    const float wgt = e / total;
    g_weights[b*Tt + tid] = wgt;
    if (w_out) w_out[b*Tt + tid] = wgt;
}

// ---------------- context = sum_t w[b,t] * features[b,t,:] ----------------
// grid (8, 128), 128 threads: 1024 blocks, unroll 8, 4 accumulators.
__global__ void __launch_bounds__(128)
context_kernel(const float* __restrict__ feat,
               float* __restrict__ ctx){
    const int b = blockIdx.y;
    const int d = blockIdx.x * 128 + threadIdx.x;
    __shared__ float sw[Tt];
    #pragma unroll
    for (int i = 0; i < 5; i++){
        const int t = threadIdx.x + i*128;
        if (t < Tt) sw[t] = g_weights[b*Tt + t];
    }
    __syncthreads();
    const float* fb = feat + (size_t)b*Tt*Dd + d;
    float a0 = 0.f, a1 = 0.f, a2 = 0.f, a3 = 0.f;
    #pragma unroll 2
    for (int t = 0; t < Tt; t += 8){
        a0 += sw[t+0] * fb[(size_t)(t+0)*Dd];
        a1 += sw[t+1] * fb[(size_t)(t+1)*Dd];
        a2 += sw[t+2] * fb[(size_t)(t+2)*Dd];
        a3 += sw[t+3] * fb[(size_t)(t+3)*Dd];
        a0 += sw[t+4] * fb[(size_t)(t+4)*Dd];
        a1 += sw[t+5] * fb[(size_t)(t+5)*Dd];
        a2 += sw[t+6] * fb[(size_t)(t+6)*Dd];
        a3 += sw[t+7] * fb[(size_t)(t+7)*Dd];
    }
    ctx[b*Dd + d] = (a0 + a1) + (a2 + a3);
}

// ---------------- launch ----------------
extern "C" void kernel_launch(void* const* d_in, const int* in_sizes, int n_in,
                              void* d_out, int out_size){
    const float* features = (const float*)d_in[0];
    const float* hidden   = (const float*)d_in[1];
    const float* W1w      = (const float*)d_in[2];
    const float* W1b      = (const float*)d_in[3];
    const float* W2w      = (const float*)d_in[4];
    const float* W2b      = (const float*)d_in[5];
    const float* Vw       = (const float*)d_in[6];
    // d_in[7] = V_b: softmax is shift-invariant -> cannot affect outputs.

    float* out = (float*)d_out;
    float* ctx_out = nullptr;
    float* w_out   = nullptr;
    if (out_size >= Bb*Dd + Mm)      { ctx_out = out; w_out = out + Bb*Dd; }
    else if (out_size == Bb*Dd)      { ctx_out = out; }
    else if (out_size == Mm)         { w_out = out; }
    else                             { ctx_out = out; }

    cudaFuncSetAttribute(gemm_score_kernel,
                         cudaFuncAttributeMaxDynamicSharedMemorySize, GEMM_SMEM);

    conv_w1_kernel<<<(Dd*Uu/4)/256, 256>>>(W1w);
    projh_kernel<<<dim3(Bb, 8), 256>>>(hidden, W2w, W2b, W1b);

    dim3 gg(Uu/BN, Mm/BM);   // (4, 288)
    gemm_score_kernel<<<gg, 256, GEMM_SMEM>>>(features, Vw);

    softmax_kernel<<<Bb, Tt>>>(w_out);

    if (ctx_out){
        dim3 gc(Dd/128, Bb); // (8, 128)
        context_kernel<<<gc, 128>>>(features, ctx_out);
    }
}